// round 1
// baseline (speedup 1.0000x reference)
#include <cuda_runtime.h>
#include <cuda_bf16.h>
#include <cstdint>

// Problem shape (from reference setup_inputs): n=4096, m=32768, d=128, L=2
#define N_FIX 4096
#define M_FIX 32768
#define D_FIX 128

#define BM 128
#define BN 128
#define BK 128
#define SSTR 136          // smem row stride in bf16 (+8 pad: conflict-free ldmatrix)
#define MARGIN 0.5f
#define POS_THRESH (1.0f - 1e-5f)

// Scratch (allocation-free rule: __device__ globals)
__device__ __nv_bfloat16 g_A[N_FIX * D_FIX];
__device__ __nv_bfloat16 g_B[M_FIX * D_FIX];
__device__ int g_labA[N_FIX];
__device__ int g_labB[M_FIX];

// ---------------------------------------------------------------------------
// Prep: fp32 -> bf16 conversion, label extraction (level 0), out zeroing
// ---------------------------------------------------------------------------
__global__ void prep_kernel(const float* __restrict__ emb,
                            const long long* __restrict__ labels,
                            const float* __restrict__ ref,
                            const long long* __restrict__ ref_labels,
                            float* __restrict__ out) {
    int tid = blockIdx.x * blockDim.x + threadIdx.x;
    int stride = gridDim.x * blockDim.x;
    if (tid == 0) out[0] = 0.0f;
    for (int i = tid; i < N_FIX * D_FIX; i += stride)
        g_A[i] = __float2bfloat16(emb[i]);
    for (int i = tid; i < M_FIX * D_FIX; i += stride)
        g_B[i] = __float2bfloat16(ref[i]);
    for (int i = tid; i < N_FIX; i += stride)
        g_labA[i] = (int)labels[(long long)i * 2];
    for (int i = tid; i < M_FIX; i += stride)
        g_labB[i] = (int)ref_labels[(long long)i * 2];
}

// ---------------------------------------------------------------------------
// ldmatrix / mma helpers
// ---------------------------------------------------------------------------
__device__ __forceinline__ uint32_t smem_u32(const void* p) {
    return (uint32_t)__cvta_generic_to_shared(p);
}

__device__ __forceinline__ void ldsm_x4(uint32_t& r0, uint32_t& r1,
                                        uint32_t& r2, uint32_t& r3, uint32_t addr) {
    asm volatile("ldmatrix.sync.aligned.m8n8.x4.shared.b16 {%0,%1,%2,%3}, [%4];"
                 : "=r"(r0), "=r"(r1), "=r"(r2), "=r"(r3) : "r"(addr));
}

__device__ __forceinline__ void ldsm_x2(uint32_t& r0, uint32_t& r1, uint32_t addr) {
    asm volatile("ldmatrix.sync.aligned.m8n8.x2.shared.b16 {%0,%1}, [%2];"
                 : "=r"(r0), "=r"(r1) : "r"(addr));
}

__device__ __forceinline__ void mma_bf16(float& c0, float& c1, float& c2, float& c3,
                                         uint32_t a0, uint32_t a1, uint32_t a2, uint32_t a3,
                                         uint32_t b0, uint32_t b1) {
    asm volatile(
        "mma.sync.aligned.m16n8k16.row.col.f32.bf16.bf16.f32 "
        "{%0,%1,%2,%3}, {%4,%5,%6,%7}, {%8,%9}, {%0,%1,%2,%3};"
        : "+f"(c0), "+f"(c1), "+f"(c2), "+f"(c3)
        : "r"(a0), "r"(a1), "r"(a2), "r"(a3), "r"(b0), "r"(b1));
}

__device__ __forceinline__ float loss_term(float s, int la, int lb) {
    if (la == lb)
        return (s < POS_THRESH) ? (1.0f - s) : 0.0f;
    else
        return (s > MARGIN) ? s : 0.0f;
}

// ---------------------------------------------------------------------------
// Main: 128x128 output tile per CTA, K=128 resident; 8 warps, 64x32 per warp.
// Fused masked-reduction epilogue; one atomicAdd per block.
// ---------------------------------------------------------------------------
__global__ __launch_bounds__(256, 2)
void xbm_main_kernel(float* __restrict__ out, float inv_n) {
    extern __shared__ __nv_bfloat16 smem[];
    __nv_bfloat16* As = smem;                    // BM x SSTR
    __nv_bfloat16* Bs = smem + BM * SSTR;        // BN x SSTR
    int* labA = (int*)(smem + 2 * BM * SSTR);    // BM
    int* labB = labA + BM;                       // BN

    const int tid  = threadIdx.x;
    const int warp = tid >> 5;
    const int lane = tid & 31;
    const int rowBase = blockIdx.y * BM;         // n dimension
    const int colBase = blockIdx.x * BN;         // m dimension

    // labels into smem
    if (tid < BM)       labA[tid]       = g_labA[rowBase + tid];
    else                labB[tid - BM]  = g_labB[colBase + tid - BM];

    // tiles into smem: 2048 16B chunks each, 256 threads x 8
#pragma unroll
    for (int i = 0; i < 8; i++) {
        int idx = tid + i * 256;                 // 0..2047
        int r = idx >> 4;
        int c = (idx & 15) << 3;
        *(uint4*)&As[r * SSTR + c] = *(const uint4*)&g_A[(rowBase + r) * D_FIX + c];
        *(uint4*)&Bs[r * SSTR + c] = *(const uint4*)&g_B[(colBase + r) * D_FIX + c];
    }
    __syncthreads();

    const int wm = (warp & 1) * 64;              // 2 row halves
    const int wn = (warp >> 1) * 32;             // 4 col groups

    float acc[4][4][4];
#pragma unroll
    for (int mi = 0; mi < 4; mi++)
#pragma unroll
        for (int ni = 0; ni < 4; ni++)
#pragma unroll
            for (int k = 0; k < 4; k++) acc[mi][ni][k] = 0.0f;

#pragma unroll
    for (int k0 = 0; k0 < BK; k0 += 16) {
        uint32_t a[4][4], b[4][2];
#pragma unroll
        for (int mi = 0; mi < 4; mi++) {
            int r = wm + mi * 16 + (lane & 15);
            int c = k0 + ((lane >> 4) << 3);
            ldsm_x4(a[mi][0], a[mi][1], a[mi][2], a[mi][3],
                    smem_u32(&As[r * SSTR + c]));
        }
#pragma unroll
        for (int ni = 0; ni < 4; ni++) {
            int r = wn + ni * 8 + (lane & 7);
            int c = k0 + ((lane >> 3) & 1) * 8;  // only lanes 0-15 matter for x2
            ldsm_x2(b[ni][0], b[ni][1], smem_u32(&Bs[r * SSTR + c]));
        }
#pragma unroll
        for (int mi = 0; mi < 4; mi++)
#pragma unroll
            for (int ni = 0; ni < 4; ni++)
                mma_bf16(acc[mi][ni][0], acc[mi][ni][1], acc[mi][ni][2], acc[mi][ni][3],
                         a[mi][0], a[mi][1], a[mi][2], a[mi][3],
                         b[ni][0], b[ni][1]);
    }

    // Epilogue: masked accumulation
    float local = 0.0f;
#pragma unroll
    for (int mi = 0; mi < 4; mi++) {
        int rbase = wm + mi * 16 + (lane >> 2);
        int la0 = labA[rbase];
        int la1 = labA[rbase + 8];
#pragma unroll
        for (int ni = 0; ni < 4; ni++) {
            int cbase = wn + ni * 8 + ((lane & 3) << 1);
            int lb0 = labB[cbase];
            int lb1 = labB[cbase + 1];
            local += loss_term(acc[mi][ni][0], la0, lb0);
            local += loss_term(acc[mi][ni][1], la0, lb1);
            local += loss_term(acc[mi][ni][2], la1, lb0);
            local += loss_term(acc[mi][ni][3], la1, lb1);
        }
    }

    // warp reduce
#pragma unroll
    for (int off = 16; off > 0; off >>= 1)
        local += __shfl_down_sync(0xFFFFFFFFu, local, off);

    __shared__ float wsum[8];
    if (lane == 0) wsum[warp] = local;
    __syncthreads();
    if (tid == 0) {
        float s = 0.0f;
#pragma unroll
        for (int i = 0; i < 8; i++) s += wsum[i];
        atomicAdd(out, s * inv_n);
    }
}

// ---------------------------------------------------------------------------
extern "C" void kernel_launch(void* const* d_in, const int* in_sizes, int n_in,
                              void* d_out, int out_size) {
    const float*     emb        = (const float*)d_in[0];
    const long long* labels     = (const long long*)d_in[1];
    const float*     ref        = (const float*)d_in[2];
    const long long* ref_labels = (const long long*)d_in[3];
    float* out = (float*)d_out;

    const int n = in_sizes[1] / 2;   // labels are [n, 2]
    const float inv_n = 1.0f / (float)n;

    const int smem_bytes = 2 * BM * SSTR * (int)sizeof(__nv_bfloat16)
                         + (BM + BN) * (int)sizeof(int);   // 70656 B
    cudaFuncSetAttribute(xbm_main_kernel,
                         cudaFuncAttributeMaxDynamicSharedMemorySize, smem_bytes);

    prep_kernel<<<2048, 256>>>(emb, labels, ref, ref_labels, out);

    dim3 grid(M_FIX / BN, N_FIX / BM);   // (256, 32)
    xbm_main_kernel<<<grid, 256, smem_bytes>>>(out, inv_n);
}